// round 10
// baseline (speedup 1.0000x reference)
#include <cuda_runtime.h>
#include <cstdint>

#define NUM_CLASSES 1000
#define FEAT_DIM    256
#define NROWS       262144
#define NBLK        256          // chunks for hierarchical counting sort
#define TW          16           // classes per scanA tile block

#define NSTAGE      3            // pipeline stages in the reduce
#define RPS         8            // rows per stage (8 KB)
#define ROW_BYTES   1024         // FEAT_DIM * 4

// Device-global scratch (no allocation allowed in kernel_launch).
__device__ alignas(16) int g_hist[NBLK * NUM_CLASSES];
__device__ alignas(16) int g_count[NUM_CLASSES];
__device__ alignas(16) int g_offset[NUM_CLASSES];
__device__ int g_idx[NROWS];

// ---------------------------------------------------------------------------
// mbarrier / bulk-async helpers
// ---------------------------------------------------------------------------
__device__ __forceinline__ uint32_t s2u(const void* p) {
    return (uint32_t)__cvta_generic_to_shared(p);
}
__device__ __forceinline__ void mbar_init(uint32_t a, uint32_t cnt) {
    asm volatile("mbarrier.init.shared.b64 [%0], %1;" :: "r"(a), "r"(cnt) : "memory");
}
__device__ __forceinline__ void mbar_expect_tx(uint32_t a, uint32_t bytes) {
    asm volatile("mbarrier.arrive.expect_tx.shared.b64 _, [%0], %1;"
                 :: "r"(a), "r"(bytes) : "memory");
}
__device__ __forceinline__ void mbar_arrive(uint32_t a) {
    asm volatile("mbarrier.arrive.shared.b64 _, [%0];" :: "r"(a) : "memory");
}
__device__ __forceinline__ void mbar_wait(uint32_t a, uint32_t parity) {
    asm volatile(
        "{\n\t.reg .pred P;\n"
        "WL%=:\n\t"
        "mbarrier.try_wait.parity.acquire.cta.shared::cta.b64 P, [%0], %1;\n\t"
        "@P bra WD%=;\n\t"
        "bra WL%=;\n"
        "WD%=:\n\t}"
        :: "r"(a), "r"(parity) : "memory");
}
__device__ __forceinline__ void bulk_ld(uint32_t dst, const void* src,
                                        uint32_t bytes, uint32_t mbar) {
    asm volatile(
        "cp.async.bulk.shared::cta.global.mbarrier::complete_tx::bytes "
        "[%0], [%1], %2, [%3];"
        :: "r"(dst), "l"(src), "r"(bytes), "r"(mbar) : "memory");
}

// ---------------------------------------------------------------------------
// Kernel 1: per-block label histogram. 1024 threads, one row per thread
// (R8 configuration: 2 blocks/SM, shortest dependent chain).
// ---------------------------------------------------------------------------
__global__ void __launch_bounds__(1024)
k_hist(const int* __restrict__ labels, int n, int rpb) {
    __shared__ int h[NUM_CLASSES];
    int t = threadIdx.x;
    for (int i = t; i < NUM_CLASSES; i += 1024) h[i] = 0;
    __syncthreads();
    int base = blockIdx.x * rpb;
    for (int j = t; j < rpb; j += 1024) {
        int r = base + j;
        if (r < n) atomicAdd(&h[labels[r]], 1);
    }
    __syncthreads();
    int* dst = &g_hist[blockIdx.x * NUM_CLASSES];
    for (int i = t; i < NUM_CLASSES; i += 1024) dst[i] = h[i];
}

// ---------------------------------------------------------------------------
// Kernel 2: per-class exclusive scan across the NBLK chunks, tiled transpose.
// Block owns TW=16 classes. Loads a NBLK x 16 tile coalesced, warp-scans
// columns (stride-17 pad: conflict-free), writes back coalesced.
// ---------------------------------------------------------------------------
__global__ void __launch_bounds__(256)
k_scanA() {
    __shared__ int tile[NBLK][TW + 1];   // 256 x 17 ints = 17.4 KB
    int t  = threadIdx.x;
    int c0 = blockIdx.x * TW;

    // Coalesced load: consecutive threads -> consecutive classes within a row.
    for (int k = t; k < NBLK * TW; k += 256) {
        int r  = k >> 4;          // chunk index
        int cc = k & (TW - 1);    // class within tile
        int c  = c0 + cc;
        tile[r][cc] = (c < NUM_CLASSES) ? g_hist[r * NUM_CLASSES + c] : 0;
    }
    __syncthreads();

    // Each warp scans 2 columns of NBLK values (8 segments of 32).
    int lane = t & 31, w = t >> 5;
    #pragma unroll
    for (int q = 0; q < 2; q++) {
        int col = w * 2 + q;
        int carry = 0;
        #pragma unroll
        for (int seg = 0; seg < NBLK / 32; seg++) {
            int x = tile[seg * 32 + lane][col];
            int incl = x;
            #pragma unroll
            for (int o = 1; o < 32; o <<= 1) {
                int y = __shfl_up_sync(0xffffffffu, incl, o);
                if (lane >= o) incl += y;
            }
            tile[seg * 32 + lane][col] = carry + incl - x;   // exclusive
            carry += __shfl_sync(0xffffffffu, incl, 31);
        }
        int c = c0 + col;
        if (lane == 0 && c < NUM_CLASSES) g_count[c] = carry;
    }
    __syncthreads();

    // Coalesced write-back.
    for (int k = t; k < NBLK * TW; k += 256) {
        int r  = k >> 4;
        int cc = k & (TW - 1);
        int c  = c0 + cc;
        if (c < NUM_CLASSES) g_hist[r * NUM_CLASSES + c] = tile[r][cc];
    }
}

// ---------------------------------------------------------------------------
// Kernel 3: exclusive scan over 1000 class totals (single block)
// ---------------------------------------------------------------------------
__global__ void k_scanB() {
    __shared__ int s[1024];
    int t = threadIdx.x;
    s[t] = (t < NUM_CLASSES) ? g_count[t] : 0;
    for (int off = 1; off < 1024; off <<= 1) {
        __syncthreads();
        int v = (t >= off) ? s[t - off] : 0;
        __syncthreads();
        s[t] += v;
    }
    __syncthreads();
    if (t < NUM_CLASSES) g_offset[t] = (t == 0) ? 0 : s[t - 1];
}

// ---------------------------------------------------------------------------
// Kernel 4: scatter. 256 blocks x 1024 threads, one row per thread
// (R8 configuration): LDG(label) -> ATOMS(cursor) -> STG(g_idx).
// ---------------------------------------------------------------------------
__global__ void __launch_bounds__(1024)
k_scatter(const int* __restrict__ labels, int n, int rpb) {
    __shared__ int cursor[NUM_CLASSES];
    int b = blockIdx.x;
    int t = threadIdx.x;
    const int* pre = &g_hist[b * NUM_CLASSES];
    for (int i = t; i < NUM_CLASSES; i += 1024)
        cursor[i] = g_offset[i] + pre[i];
    __syncthreads();
    int base = b * rpb;
    for (int j = t; j < rpb; j += 1024) {
        int r = base + j;
        if (r < n) {
            int c = labels[r];
            g_idx[atomicAdd(&cursor[c], 1)] = r;
        }
    }
}

// ---------------------------------------------------------------------------
// Kernel 5: warp-specialized pipelined reduce (unchanged; proven).
// 288 threads = 8 consumer warps (256 thr) + 1 producer warp.
// ---------------------------------------------------------------------------
__global__ void __launch_bounds__(288, 7)
k_reduce(const char* __restrict__ featsB,
         const float* __restrict__ protos,
         float* __restrict__ out) {
    __shared__ float4 stage[NSTAGE][RPS * 64];          // 3 x 8KB
    __shared__ float4 part4[4][64];                     // 4KB combine buffer
    __shared__ alignas(8) unsigned long long mbar[2 * NSTAGE]; // full/empty pairs

    int c = blockIdx.x;
    int t = threadIdx.x;
    int start = g_offset[c];
    int cnt   = g_count[c];
    int nIter = (cnt + RPS - 1) / RPS;

    if (t == 0) {
        #pragma unroll
        for (int s = 0; s < NSTAGE; s++) {
            mbar_init(s2u(&mbar[2 * s]), 1);        // full: tx-completion
            mbar_init(s2u(&mbar[2 * s + 1]), 8);    // empty: 8 consumer warps
        }
    }
    __syncthreads();

    if (t >= 256) {
        // ---- producer warp ----
        int lane = t - 256;
        int idxReg = 0;
        int s = 0, wrap = 0;
        for (int i = 0; i < nIter; i++) {
            if ((i & 3) == 0) {           // refill 32 indices (4 iterations worth)
                int p = i * RPS + lane;
                idxReg = (p < cnt) ? g_idx[start + p] : 0;
            }
            if (wrap > 0)
                mbar_wait(s2u(&mbar[2 * s + 1]), (unsigned)((wrap - 1) & 1));
            int m = min(RPS, cnt - i * RPS);
            int row = __shfl_sync(0xffffffffu, idxReg, ((i & 3) << 3) + (lane & 7));
            if (lane == 0)
                mbar_expect_tx(s2u(&mbar[2 * s]), (uint32_t)m * ROW_BYTES);
            __syncwarp();
            if (lane < m)
                bulk_ld(s2u(&stage[s][0]) + (uint32_t)lane * ROW_BYTES,
                        featsB + (long)row * ROW_BYTES,
                        ROW_BYTES, s2u(&mbar[2 * s]));
            if (++s == NSTAGE) { s = 0; wrap++; }
        }
    } else {
        // ---- consumer warps ----
        int grp = t >> 6;     // 0..3
        int col = t & 63;
        float4 a0 = make_float4(0.f, 0.f, 0.f, 0.f);
        float4 a1 = make_float4(0.f, 0.f, 0.f, 0.f);
        int s = 0, ph = 0;
        for (int i = 0; i < nIter; i++) {
            mbar_wait(s2u(&mbar[2 * s]), (unsigned)ph);
            int m = min(RPS, cnt - i * RPS);
            if (grp < m) {
                float4 v = stage[s][grp * 64 + col];
                a0.x += v.x; a0.y += v.y; a0.z += v.z; a0.w += v.w;
            }
            if (grp + 4 < m) {
                float4 v = stage[s][(grp + 4) * 64 + col];
                a1.x += v.x; a1.y += v.y; a1.z += v.z; a1.w += v.w;
            }
            __syncwarp();
            if ((t & 31) == 0) mbar_arrive(s2u(&mbar[2 * s + 1]));
            if (++s == NSTAGE) { s = 0; ph ^= 1; }
        }
        float4 a = make_float4(a0.x + a1.x, a0.y + a1.y,
                               a0.z + a1.z, a0.w + a1.w);
        part4[grp][col] = a;
    }

    __syncthreads();

    if (t < 256) {
        const float* part = (const float*)part4;   // part[g*256 + column]
        float sum = (part[0 * 256 + t] + part[1 * 256 + t])
                  + (part[2 * 256 + t] + part[3 * 256 + t]);
        float p = protos[c * FEAT_DIM + t];
        float r = p;
        if (cnt > 0) {
            float mean = sum / (float)cnt;
            r = 0.9f * p + 0.1f * mean;
        }
        out[c * FEAT_DIM + t] = r;
    }
}

// ---------------------------------------------------------------------------
// Launch
// ---------------------------------------------------------------------------
extern "C" void kernel_launch(void* const* d_in, const int* in_sizes, int n_in,
                              void* d_out, int out_size) {
    const float* features   = (const float*)d_in[0];
    const int*   labels     = (const int*)d_in[1];
    const float* prototypes = (const float*)d_in[2];
    float*       out        = (float*)d_out;

    int n   = in_sizes[1];
    int rpb = (n + NBLK - 1) / NBLK;                 // rows per block-chunk
    int nScanBlocks = (NUM_CLASSES + TW - 1) / TW;   // 63

    k_hist   <<<NBLK, 1024>>>(labels, n, rpb);
    k_scanA  <<<nScanBlocks, 256>>>();
    k_scanB  <<<1, 1024>>>();
    k_scatter<<<NBLK, 1024>>>(labels, n, rpb);
    k_reduce <<<NUM_CLASSES, 288>>>((const char*)features, prototypes, out);
}

// round 11
// speedup vs baseline: 1.0442x; 1.0442x over previous
#include <cuda_runtime.h>
#include <cstdint>

#define NUM_CLASSES 1000
#define FEAT_DIM    256
#define NROWS       262144
#define NBLK        256          // chunks for hierarchical counting sort

#define NSTAGE      3            // pipeline stages in the reduce
#define RPS         8            // rows per stage (8 KB)
#define ROW_BYTES   1024         // FEAT_DIM * 4
#define NCONS       128          // consumer threads (4 warps)

// Device-global scratch (no allocation allowed in kernel_launch).
__device__ alignas(16) int g_hist[NBLK * NUM_CLASSES];
__device__ alignas(16) int g_count[NUM_CLASSES];
__device__ alignas(16) int g_offset[NUM_CLASSES];
__device__ int g_idx[NROWS];

// ---------------------------------------------------------------------------
// mbarrier / bulk-async helpers
// ---------------------------------------------------------------------------
__device__ __forceinline__ uint32_t s2u(const void* p) {
    return (uint32_t)__cvta_generic_to_shared(p);
}
__device__ __forceinline__ void mbar_init(uint32_t a, uint32_t cnt) {
    asm volatile("mbarrier.init.shared.b64 [%0], %1;" :: "r"(a), "r"(cnt) : "memory");
}
__device__ __forceinline__ void mbar_expect_tx(uint32_t a, uint32_t bytes) {
    asm volatile("mbarrier.arrive.expect_tx.shared.b64 _, [%0], %1;"
                 :: "r"(a), "r"(bytes) : "memory");
}
__device__ __forceinline__ void mbar_arrive(uint32_t a) {
    asm volatile("mbarrier.arrive.shared.b64 _, [%0];" :: "r"(a) : "memory");
}
__device__ __forceinline__ void mbar_wait(uint32_t a, uint32_t parity) {
    asm volatile(
        "{\n\t.reg .pred P;\n"
        "WL%=:\n\t"
        "mbarrier.try_wait.parity.acquire.cta.shared::cta.b64 P, [%0], %1;\n\t"
        "@P bra WD%=;\n\t"
        "bra WL%=;\n"
        "WD%=:\n\t}"
        :: "r"(a), "r"(parity) : "memory");
}
__device__ __forceinline__ void bulk_ld(uint32_t dst, const void* src,
                                        uint32_t bytes, uint32_t mbar) {
    asm volatile(
        "cp.async.bulk.shared::cta.global.mbarrier::complete_tx::bytes "
        "[%0], [%1], %2, [%3];"
        :: "r"(dst), "l"(src), "r"(bytes), "r"(mbar) : "memory");
}

// ---------------------------------------------------------------------------
// Kernel 1: per-block label histogram. 1024 threads, one row per thread
// (R8 configuration, measured best).
// ---------------------------------------------------------------------------
__global__ void __launch_bounds__(1024)
k_hist(const int* __restrict__ labels, int n, int rpb) {
    __shared__ int h[NUM_CLASSES];
    int t = threadIdx.x;
    for (int i = t; i < NUM_CLASSES; i += 1024) h[i] = 0;
    __syncthreads();
    int base = blockIdx.x * rpb;
    for (int j = t; j < rpb; j += 1024) {
        int r = base + j;
        if (r < n) atomicAdd(&h[labels[r]], 1);
    }
    __syncthreads();
    int* dst = &g_hist[blockIdx.x * NUM_CLASSES];
    for (int i = t; i < NUM_CLASSES; i += 1024) dst[i] = h[i];
}

// ---------------------------------------------------------------------------
// Kernel 2: per-class exclusive scan across the NBLK chunks (R8 original:
// 1000 blocks of 256 threads — uncoalesced loads fully hidden by TLP).
// ---------------------------------------------------------------------------
__global__ void k_scanA() {
    int c = blockIdx.x;
    int t = threadIdx.x;
    int v = g_hist[t * NUM_CLASSES + c];

    int lane = t & 31, w = t >> 5;
    int x = v;
    #pragma unroll
    for (int o = 1; o < 32; o <<= 1) {
        int y = __shfl_up_sync(0xffffffffu, x, o);
        if (lane >= o) x += y;
    }
    __shared__ int wt[NBLK / 32];
    if (lane == 31) wt[w] = x;
    __syncthreads();
    if (t == 0) {
        int s = 0;
        #pragma unroll
        for (int i = 0; i < NBLK / 32; i++) { int tmp = wt[i]; wt[i] = s; s += tmp; }
    }
    __syncthreads();
    int incl = x + wt[w];
    g_hist[t * NUM_CLASSES + c] = incl - v;   // exclusive prefix within class
    if (t == NBLK - 1) g_count[c] = incl;     // class total
}

// ---------------------------------------------------------------------------
// Kernel 3: exclusive scan over 1000 class totals (single block)
// ---------------------------------------------------------------------------
__global__ void k_scanB() {
    __shared__ int s[1024];
    int t = threadIdx.x;
    s[t] = (t < NUM_CLASSES) ? g_count[t] : 0;
    for (int off = 1; off < 1024; off <<= 1) {
        __syncthreads();
        int v = (t >= off) ? s[t - off] : 0;
        __syncthreads();
        s[t] += v;
    }
    __syncthreads();
    if (t < NUM_CLASSES) g_offset[t] = (t == 0) ? 0 : s[t - 1];
}

// ---------------------------------------------------------------------------
// Kernel 4: scatter. 256 blocks x 1024 threads, one row per thread
// (R8 configuration): LDG(label) -> ATOMS(cursor) -> STG(g_idx).
// ---------------------------------------------------------------------------
__global__ void __launch_bounds__(1024)
k_scatter(const int* __restrict__ labels, int n, int rpb) {
    __shared__ int cursor[NUM_CLASSES];
    int b = blockIdx.x;
    int t = threadIdx.x;
    const int* pre = &g_hist[b * NUM_CLASSES];
    for (int i = t; i < NUM_CLASSES; i += 1024)
        cursor[i] = g_offset[i] + pre[i];
    __syncthreads();
    int base = b * rpb;
    for (int j = t; j < rpb; j += 1024) {
        int r = base + j;
        if (r < n) {
            int c = labels[r];
            g_idx[atomicAdd(&cursor[c], 1)] = r;
        }
    }
}

// ---------------------------------------------------------------------------
// Kernel 5: warp-specialized pipelined reduce.
// 160 threads = 4 consumer warps (128 thr) + 1 producer warp.
// Slimmer block -> 8 blocks/SM (smem-capped) -> 192KB bulk-copy bytes in
// flight per SM (was 168KB at 7 blocks). Each consumer thread absorbs 4 rows
// per stage (rows grp, grp+2, grp+4, grp+6).
// ---------------------------------------------------------------------------
__global__ void __launch_bounds__(160, 8)
k_reduce(const char* __restrict__ featsB,
         const float* __restrict__ protos,
         float* __restrict__ out) {
    __shared__ float4 stage[NSTAGE][RPS * 64];          // 3 x 8KB
    __shared__ float4 part4[2][64];                     // 2KB combine buffer
    __shared__ alignas(8) unsigned long long mbar[2 * NSTAGE]; // full/empty pairs

    int c = blockIdx.x;
    int t = threadIdx.x;
    int start = g_offset[c];
    int cnt   = g_count[c];
    int nIter = (cnt + RPS - 1) / RPS;

    if (t == 0) {
        #pragma unroll
        for (int s = 0; s < NSTAGE; s++) {
            mbar_init(s2u(&mbar[2 * s]), 1);        // full: tx-completion
            mbar_init(s2u(&mbar[2 * s + 1]), 4);    // empty: 4 consumer warps
        }
    }
    __syncthreads();

    if (t >= NCONS) {
        // ---- producer warp ----
        int lane = t - NCONS;
        int idxReg = 0;
        int s = 0, wrap = 0;
        for (int i = 0; i < nIter; i++) {
            if ((i & 3) == 0) {           // refill 32 indices (4 iterations worth)
                int p = i * RPS + lane;
                idxReg = (p < cnt) ? g_idx[start + p] : 0;
            }
            if (wrap > 0)
                mbar_wait(s2u(&mbar[2 * s + 1]), (unsigned)((wrap - 1) & 1));
            int m = min(RPS, cnt - i * RPS);
            int row = __shfl_sync(0xffffffffu, idxReg, ((i & 3) << 3) + (lane & 7));
            if (lane == 0)
                mbar_expect_tx(s2u(&mbar[2 * s]), (uint32_t)m * ROW_BYTES);
            __syncwarp();
            if (lane < m)
                bulk_ld(s2u(&stage[s][0]) + (uint32_t)lane * ROW_BYTES,
                        featsB + (long)row * ROW_BYTES,
                        ROW_BYTES, s2u(&mbar[2 * s]));
            if (++s == NSTAGE) { s = 0; wrap++; }
        }
    } else {
        // ---- consumer warps (4 warps, 128 threads) ----
        int grp = t >> 6;     // 0..1
        int col = t & 63;
        float4 a0 = make_float4(0.f, 0.f, 0.f, 0.f);
        float4 a1 = make_float4(0.f, 0.f, 0.f, 0.f);
        float4 a2 = make_float4(0.f, 0.f, 0.f, 0.f);
        float4 a3 = make_float4(0.f, 0.f, 0.f, 0.f);
        int s = 0, ph = 0;
        for (int i = 0; i < nIter; i++) {
            mbar_wait(s2u(&mbar[2 * s]), (unsigned)ph);
            int m = min(RPS, cnt - i * RPS);
            if (grp < m) {
                float4 v = stage[s][grp * 64 + col];
                a0.x += v.x; a0.y += v.y; a0.z += v.z; a0.w += v.w;
            }
            if (grp + 2 < m) {
                float4 v = stage[s][(grp + 2) * 64 + col];
                a1.x += v.x; a1.y += v.y; a1.z += v.z; a1.w += v.w;
            }
            if (grp + 4 < m) {
                float4 v = stage[s][(grp + 4) * 64 + col];
                a2.x += v.x; a2.y += v.y; a2.z += v.z; a2.w += v.w;
            }
            if (grp + 6 < m) {
                float4 v = stage[s][(grp + 6) * 64 + col];
                a3.x += v.x; a3.y += v.y; a3.z += v.z; a3.w += v.w;
            }
            __syncwarp();
            if ((t & 31) == 0) mbar_arrive(s2u(&mbar[2 * s + 1]));
            if (++s == NSTAGE) { s = 0; ph ^= 1; }
        }
        float4 a = make_float4((a0.x + a1.x) + (a2.x + a3.x),
                               (a0.y + a1.y) + (a2.y + a3.y),
                               (a0.z + a1.z) + (a2.z + a3.z),
                               (a0.w + a1.w) + (a2.w + a3.w));
        part4[grp][col] = a;
    }

    __syncthreads();

    if (t < NCONS) {
        const float* part = (const float*)part4;   // part[g*256 + column]
        float inv = (cnt > 0) ? 0.1f / (float)cnt : 0.f;
        #pragma unroll
        for (int k = 0; k < 2; k++) {
            int d = t + k * NCONS;                 // output column 0..255
            float sum = part[0 * 256 + d] + part[1 * 256 + d];
            float p = protos[c * FEAT_DIM + d];
            float r = (cnt > 0) ? (0.9f * p + sum * inv) : p;
            out[c * FEAT_DIM + d] = r;
        }
    }
}

// ---------------------------------------------------------------------------
// Launch
// ---------------------------------------------------------------------------
extern "C" void kernel_launch(void* const* d_in, const int* in_sizes, int n_in,
                              void* d_out, int out_size) {
    const float* features   = (const float*)d_in[0];
    const int*   labels     = (const int*)d_in[1];
    const float* prototypes = (const float*)d_in[2];
    float*       out        = (float*)d_out;

    int n   = in_sizes[1];
    int rpb = (n + NBLK - 1) / NBLK;   // rows per block-chunk

    k_hist   <<<NBLK, 1024>>>(labels, n, rpb);
    k_scanA  <<<NUM_CLASSES, NBLK>>>();
    k_scanB  <<<1, 1024>>>();
    k_scatter<<<NBLK, 1024>>>(labels, n, rpb);
    k_reduce <<<NUM_CLASSES, 160>>>((const char*)features, prototypes, out);
}

// round 12
// speedup vs baseline: 1.1946x; 1.1440x over previous
#include <cuda_runtime.h>
#include <cstdint>

#define NUM_CLASSES 1000
#define FEAT_DIM    256
#define NROWS       262144
#define NBLK        256          // row chunks (one fused-scatter block each)
#define CAP         512          // bucket capacity per class (max count ~330)

#define NSTAGE      3            // pipeline stages in the reduce
#define RPS         8            // rows per stage (8 KB)
#define ROW_BYTES   1024         // FEAT_DIM * 4
#define NCONS       128          // consumer threads (4 warps)

// Device-global scratch (no allocation allowed in kernel_launch).
// g_count starts zeroed (static init) and is re-zeroed by k_reduce each call,
// so graph replays always begin from a clean state.
__device__ alignas(16) int g_count[NUM_CLASSES];
__device__ int g_idx[NUM_CLASSES * CAP];     // 2 MB bucket array

// ---------------------------------------------------------------------------
// mbarrier / bulk-async helpers
// ---------------------------------------------------------------------------
__device__ __forceinline__ uint32_t s2u(const void* p) {
    return (uint32_t)__cvta_generic_to_shared(p);
}
__device__ __forceinline__ void mbar_init(uint32_t a, uint32_t cnt) {
    asm volatile("mbarrier.init.shared.b64 [%0], %1;" :: "r"(a), "r"(cnt) : "memory");
}
__device__ __forceinline__ void mbar_expect_tx(uint32_t a, uint32_t bytes) {
    asm volatile("mbarrier.arrive.expect_tx.shared.b64 _, [%0], %1;"
                 :: "r"(a), "r"(bytes) : "memory");
}
__device__ __forceinline__ void mbar_arrive(uint32_t a) {
    asm volatile("mbarrier.arrive.shared.b64 _, [%0];" :: "r"(a) : "memory");
}
__device__ __forceinline__ void mbar_wait(uint32_t a, uint32_t parity) {
    asm volatile(
        "{\n\t.reg .pred P;\n"
        "WL%=:\n\t"
        "mbarrier.try_wait.parity.acquire.cta.shared::cta.b64 P, [%0], %1;\n\t"
        "@P bra WD%=;\n\t"
        "bra WL%=;\n"
        "WD%=:\n\t}"
        :: "r"(a), "r"(parity) : "memory");
}
__device__ __forceinline__ void bulk_ld(uint32_t dst, const void* src,
                                        uint32_t bytes, uint32_t mbar) {
    asm volatile(
        "cp.async.bulk.shared::cta.global.mbarrier::complete_tx::bytes "
        "[%0], [%1], %2, [%3];"
        :: "r"(dst), "l"(src), "r"(bytes), "r"(mbar) : "memory");
}

// ---------------------------------------------------------------------------
// Kernel 1 (fused prep): per-chunk hist -> bucket reservation -> scatter.
// 256 blocks x 1024 threads, one row per thread.
//   Phase A: smem histogram of this chunk's labels.
//   Phase B: one atomicAdd(&g_count[c], h[c]) per present class reserves a
//            contiguous range in class c's bucket; base overwrites h[c].
//   Phase C: scatter rows via smem cursors into g_idx[c*CAP + base + k].
// Order within a class is nondeterministic across blocks — irrelevant, the
// reduce sums the segment (permutation-invariant to 1e-3 tolerance).
// ---------------------------------------------------------------------------
__global__ void __launch_bounds__(1024)
k_prep(const int* __restrict__ labels, int n, int rpb) {
    __shared__ int h[NUM_CLASSES];
    int b = blockIdx.x;
    int t = threadIdx.x;
    int base = b * rpb;

    for (int i = t; i < NUM_CLASSES; i += 1024) h[i] = 0;
    __syncthreads();

    // Phase A: histogram (labels land in L2 for the phase-C reload).
    for (int j = t; j < rpb; j += 1024) {
        int r = base + j;
        if (r < n) atomicAdd(&h[labels[r]], 1);
    }
    __syncthreads();

    // Phase B: reserve ranges; h[c] becomes this block's cursor base.
    for (int c = t; c < NUM_CLASSES; c += 1024) {
        int v = h[c];
        h[c] = (v > 0) ? atomicAdd(&g_count[c], v) : 0;
    }
    __syncthreads();

    // Phase C: scatter.
    for (int j = t; j < rpb; j += 1024) {
        int r = base + j;
        if (r < n) {
            int c = labels[r];
            int pos = atomicAdd(&h[c], 1);
            g_idx[c * CAP + pos] = r;
        }
    }
}

// ---------------------------------------------------------------------------
// Kernel 2: warp-specialized pipelined reduce (proven R8/R11 mainloop).
// 160 threads = 4 consumer warps + 1 producer warp. Class c's rows live in
// g_idx[c*CAP .. c*CAP+cnt). Resets g_count[c] for the next graph replay.
// ---------------------------------------------------------------------------
__global__ void __launch_bounds__(160, 8)
k_reduce(const char* __restrict__ featsB,
         const float* __restrict__ protos,
         float* __restrict__ out) {
    __shared__ float4 stage[NSTAGE][RPS * 64];          // 3 x 8KB
    __shared__ float4 part4[2][64];                     // 2KB combine buffer
    __shared__ alignas(8) unsigned long long mbar[2 * NSTAGE]; // full/empty pairs

    int c = blockIdx.x;
    int t = threadIdx.x;
    int start = c * CAP;
    int cnt   = g_count[c];
    int nIter = (cnt + RPS - 1) / RPS;

    if (t == 0) {
        #pragma unroll
        for (int s = 0; s < NSTAGE; s++) {
            mbar_init(s2u(&mbar[2 * s]), 1);        // full: tx-completion
            mbar_init(s2u(&mbar[2 * s + 1]), 4);    // empty: 4 consumer warps
        }
    }
    __syncthreads();
    // All threads hold cnt in a register now; safe to reset for next replay.
    if (t == 0) g_count[c] = 0;

    if (t >= NCONS) {
        // ---- producer warp ----
        int lane = t - NCONS;
        int idxReg = 0;
        int s = 0, wrap = 0;
        for (int i = 0; i < nIter; i++) {
            if ((i & 3) == 0) {           // refill 32 indices (4 iterations worth)
                int p = i * RPS + lane;
                idxReg = (p < cnt) ? g_idx[start + p] : 0;
            }
            if (wrap > 0)
                mbar_wait(s2u(&mbar[2 * s + 1]), (unsigned)((wrap - 1) & 1));
            int m = min(RPS, cnt - i * RPS);
            int row = __shfl_sync(0xffffffffu, idxReg, ((i & 3) << 3) + (lane & 7));
            if (lane == 0)
                mbar_expect_tx(s2u(&mbar[2 * s]), (uint32_t)m * ROW_BYTES);
            __syncwarp();
            if (lane < m)
                bulk_ld(s2u(&stage[s][0]) + (uint32_t)lane * ROW_BYTES,
                        featsB + (long)row * ROW_BYTES,
                        ROW_BYTES, s2u(&mbar[2 * s]));
            if (++s == NSTAGE) { s = 0; wrap++; }
        }
    } else {
        // ---- consumer warps (4 warps, 128 threads) ----
        int grp = t >> 6;     // 0..1
        int col = t & 63;
        float4 a0 = make_float4(0.f, 0.f, 0.f, 0.f);
        float4 a1 = make_float4(0.f, 0.f, 0.f, 0.f);
        float4 a2 = make_float4(0.f, 0.f, 0.f, 0.f);
        float4 a3 = make_float4(0.f, 0.f, 0.f, 0.f);
        int s = 0, ph = 0;
        for (int i = 0; i < nIter; i++) {
            mbar_wait(s2u(&mbar[2 * s]), (unsigned)ph);
            int m = min(RPS, cnt - i * RPS);
            if (grp < m) {
                float4 v = stage[s][grp * 64 + col];
                a0.x += v.x; a0.y += v.y; a0.z += v.z; a0.w += v.w;
            }
            if (grp + 2 < m) {
                float4 v = stage[s][(grp + 2) * 64 + col];
                a1.x += v.x; a1.y += v.y; a1.z += v.z; a1.w += v.w;
            }
            if (grp + 4 < m) {
                float4 v = stage[s][(grp + 4) * 64 + col];
                a2.x += v.x; a2.y += v.y; a2.z += v.z; a2.w += v.w;
            }
            if (grp + 6 < m) {
                float4 v = stage[s][(grp + 6) * 64 + col];
                a3.x += v.x; a3.y += v.y; a3.z += v.z; a3.w += v.w;
            }
            __syncwarp();
            if ((t & 31) == 0) mbar_arrive(s2u(&mbar[2 * s + 1]));
            if (++s == NSTAGE) { s = 0; ph ^= 1; }
        }
        float4 a = make_float4((a0.x + a1.x) + (a2.x + a3.x),
                               (a0.y + a1.y) + (a2.y + a3.y),
                               (a0.z + a1.z) + (a2.z + a3.z),
                               (a0.w + a1.w) + (a2.w + a3.w));
        part4[grp][col] = a;
    }

    __syncthreads();

    if (t < NCONS) {
        const float* part = (const float*)part4;   // part[g*256 + column]
        float inv = (cnt > 0) ? 0.1f / (float)cnt : 0.f;
        #pragma unroll
        for (int k = 0; k < 2; k++) {
            int d = t + k * NCONS;                 // output column 0..255
            float sum = part[0 * 256 + d] + part[1 * 256 + d];
            float p = protos[c * FEAT_DIM + d];
            float r = (cnt > 0) ? (0.9f * p + sum * inv) : p;
            out[c * FEAT_DIM + d] = r;
        }
    }
}

// ---------------------------------------------------------------------------
// Launch: two kernels total.
// ---------------------------------------------------------------------------
extern "C" void kernel_launch(void* const* d_in, const int* in_sizes, int n_in,
                              void* d_out, int out_size) {
    const float* features   = (const float*)d_in[0];
    const int*   labels     = (const int*)d_in[1];
    const float* prototypes = (const float*)d_in[2];
    float*       out        = (float*)d_out;

    int n   = in_sizes[1];
    int rpb = (n + NBLK - 1) / NBLK;   // rows per block-chunk (1024)

    k_prep  <<<NBLK, 1024>>>(labels, n, rpb);
    k_reduce<<<NUM_CLASSES, 160>>>((const char*)features, prototypes, out);
}

// round 13
// speedup vs baseline: 1.2025x; 1.0066x over previous
#include <cuda_runtime.h>
#include <cstdint>

#define NUM_CLASSES 1000
#define FEAT_DIM    256
#define NROWS       262144
#define NBLK        256          // row chunks (one fused-scatter block each)
#define CAP         512          // bucket capacity per class (max count ~330)
#define LAB_CAP     2048         // smem label cache capacity

#define NSTAGE      3            // pipeline stages in the reduce
#define RPS         8            // rows per stage (8 KB)
#define ROW_BYTES   1024         // FEAT_DIM * 4
#define NCONS       128          // consumer threads (4 warps)

// Device-global scratch (no allocation allowed in kernel_launch).
// g_count starts zeroed (static init) and is re-zeroed by k_reduce each call,
// so graph replays always begin from a clean state.
__device__ alignas(16) int g_count[NUM_CLASSES];
__device__ int g_idx[NUM_CLASSES * CAP];     // 2 MB bucket array

// ---------------------------------------------------------------------------
// mbarrier / bulk-async helpers
// ---------------------------------------------------------------------------
__device__ __forceinline__ uint32_t s2u(const void* p) {
    return (uint32_t)__cvta_generic_to_shared(p);
}
__device__ __forceinline__ void mbar_init(uint32_t a, uint32_t cnt) {
    asm volatile("mbarrier.init.shared.b64 [%0], %1;" :: "r"(a), "r"(cnt) : "memory");
}
__device__ __forceinline__ void mbar_expect_tx(uint32_t a, uint32_t bytes) {
    asm volatile("mbarrier.arrive.expect_tx.shared.b64 _, [%0], %1;"
                 :: "r"(a), "r"(bytes) : "memory");
}
__device__ __forceinline__ void mbar_arrive(uint32_t a) {
    asm volatile("mbarrier.arrive.shared.b64 _, [%0];" :: "r"(a) : "memory");
}
__device__ __forceinline__ void mbar_wait(uint32_t a, uint32_t parity) {
    asm volatile(
        "{\n\t.reg .pred P;\n"
        "WL%=:\n\t"
        "mbarrier.try_wait.parity.acquire.cta.shared::cta.b64 P, [%0], %1;\n\t"
        "@P bra WD%=;\n\t"
        "bra WL%=;\n"
        "WD%=:\n\t}"
        :: "r"(a), "r"(parity) : "memory");
}
__device__ __forceinline__ void bulk_ld(uint32_t dst, const void* src,
                                        uint32_t bytes, uint32_t mbar) {
    asm volatile(
        "cp.async.bulk.shared::cta.global.mbarrier::complete_tx::bytes "
        "[%0], [%1], %2, [%3];"
        :: "r"(dst), "l"(src), "r"(bytes), "r"(mbar) : "memory");
}

// ---------------------------------------------------------------------------
// Kernel 1 (fused prep): per-chunk hist -> bucket reservation -> scatter.
// 256 blocks x 1024 threads, one row per thread.
//   Phase A: smem histogram + smem label cache (single global label read).
//   Phase B: one atomicAdd(&g_count[c], h[c]) per present class reserves a
//            contiguous range in class c's bucket; base overwrites h[c].
//   Phase C: scatter rows via smem cursors into g_idx[c*CAP + base + k],
//            labels re-read from smem (no second global round-trip).
// ---------------------------------------------------------------------------
__global__ void __launch_bounds__(1024)
k_prep(const int* __restrict__ labels, int n, int rpb) {
    __shared__ int h[NUM_CLASSES];
    __shared__ int lab[LAB_CAP];
    int b = blockIdx.x;
    int t = threadIdx.x;
    int base = b * rpb;
    bool cache = (rpb <= LAB_CAP);

    for (int i = t; i < NUM_CLASSES; i += 1024) h[i] = 0;
    __syncthreads();

    // Phase A: histogram + label caching.
    for (int j = t; j < rpb; j += 1024) {
        int r = base + j;
        int c = (r < n) ? labels[r] : -1;
        if (cache) lab[j] = c;
        if (c >= 0) atomicAdd(&h[c], 1);
    }
    __syncthreads();

    // Phase B: reserve ranges; h[c] becomes this block's cursor base.
    for (int c = t; c < NUM_CLASSES; c += 1024) {
        int v = h[c];
        h[c] = (v > 0) ? atomicAdd(&g_count[c], v) : 0;
    }
    __syncthreads();

    // Phase C: scatter (labels from smem).
    for (int j = t; j < rpb; j += 1024) {
        int r = base + j;
        if (r < n) {
            int c = cache ? lab[j] : labels[r];
            int pos = atomicAdd(&h[c], 1);
            g_idx[c * CAP + pos] = r;
        }
    }
}

// ---------------------------------------------------------------------------
// Kernel 2: warp-specialized pipelined reduce (proven R12 mainloop).
// 160 threads = 4 consumer warps + 1 producer warp. Class c's rows live in
// g_idx[c*CAP .. c*CAP+cnt). Resets g_count[c] for the next graph replay.
// Protos are prefetched into registers before the mainloop.
// ---------------------------------------------------------------------------
__global__ void __launch_bounds__(160, 8)
k_reduce(const char* __restrict__ featsB,
         const float* __restrict__ protos,
         float* __restrict__ out) {
    __shared__ float4 stage[NSTAGE][RPS * 64];          // 3 x 8KB
    __shared__ float4 part4[2][64];                     // 2KB combine buffer
    __shared__ alignas(8) unsigned long long mbar[2 * NSTAGE]; // full/empty pairs

    int c = blockIdx.x;
    int t = threadIdx.x;
    int start = c * CAP;
    int cnt   = g_count[c];
    int nIter = (cnt + RPS - 1) / RPS;

    // Prefetch prototypes early (consumer threads own the epilogue).
    float p0 = 0.f, p1 = 0.f;
    if (t < NCONS) {
        p0 = protos[c * FEAT_DIM + t];
        p1 = protos[c * FEAT_DIM + t + NCONS];
    }

    if (t == 0) {
        #pragma unroll
        for (int s = 0; s < NSTAGE; s++) {
            mbar_init(s2u(&mbar[2 * s]), 1);        // full: tx-completion
            mbar_init(s2u(&mbar[2 * s + 1]), 4);    // empty: 4 consumer warps
        }
    }
    __syncthreads();
    // All threads hold cnt in a register now; safe to reset for next replay.
    if (t == 0) g_count[c] = 0;

    if (t >= NCONS) {
        // ---- producer warp ----
        int lane = t - NCONS;
        int idxReg = 0;
        int s = 0, wrap = 0;
        for (int i = 0; i < nIter; i++) {
            if ((i & 3) == 0) {           // refill 32 indices (4 iterations worth)
                int p = i * RPS + lane;
                idxReg = (p < cnt) ? g_idx[start + p] : 0;
            }
            if (wrap > 0)
                mbar_wait(s2u(&mbar[2 * s + 1]), (unsigned)((wrap - 1) & 1));
            int m = min(RPS, cnt - i * RPS);
            int row = __shfl_sync(0xffffffffu, idxReg, ((i & 3) << 3) + (lane & 7));
            if (lane == 0)
                mbar_expect_tx(s2u(&mbar[2 * s]), (uint32_t)m * ROW_BYTES);
            __syncwarp();
            if (lane < m)
                bulk_ld(s2u(&stage[s][0]) + (uint32_t)lane * ROW_BYTES,
                        featsB + (long)row * ROW_BYTES,
                        ROW_BYTES, s2u(&mbar[2 * s]));
            if (++s == NSTAGE) { s = 0; wrap++; }
        }
    } else {
        // ---- consumer warps (4 warps, 128 threads) ----
        int grp = t >> 6;     // 0..1
        int col = t & 63;
        float4 a0 = make_float4(0.f, 0.f, 0.f, 0.f);
        float4 a1 = make_float4(0.f, 0.f, 0.f, 0.f);
        float4 a2 = make_float4(0.f, 0.f, 0.f, 0.f);
        float4 a3 = make_float4(0.f, 0.f, 0.f, 0.f);
        int s = 0, ph = 0;
        for (int i = 0; i < nIter; i++) {
            mbar_wait(s2u(&mbar[2 * s]), (unsigned)ph);
            int m = min(RPS, cnt - i * RPS);
            if (grp < m) {
                float4 v = stage[s][grp * 64 + col];
                a0.x += v.x; a0.y += v.y; a0.z += v.z; a0.w += v.w;
            }
            if (grp + 2 < m) {
                float4 v = stage[s][(grp + 2) * 64 + col];
                a1.x += v.x; a1.y += v.y; a1.z += v.z; a1.w += v.w;
            }
            if (grp + 4 < m) {
                float4 v = stage[s][(grp + 4) * 64 + col];
                a2.x += v.x; a2.y += v.y; a2.z += v.z; a2.w += v.w;
            }
            if (grp + 6 < m) {
                float4 v = stage[s][(grp + 6) * 64 + col];
                a3.x += v.x; a3.y += v.y; a3.z += v.z; a3.w += v.w;
            }
            __syncwarp();
            if ((t & 31) == 0) mbar_arrive(s2u(&mbar[2 * s + 1]));
            if (++s == NSTAGE) { s = 0; ph ^= 1; }
        }
        float4 a = make_float4((a0.x + a1.x) + (a2.x + a3.x),
                               (a0.y + a1.y) + (a2.y + a3.y),
                               (a0.z + a1.z) + (a2.z + a3.z),
                               (a0.w + a1.w) + (a2.w + a3.w));
        part4[grp][col] = a;
    }

    __syncthreads();

    if (t < NCONS) {
        const float* part = (const float*)part4;   // part[g*256 + column]
        float inv = (cnt > 0) ? 0.1f / (float)cnt : 0.f;
        float s0 = part[0 * 256 + t] + part[1 * 256 + t];
        float s1 = part[0 * 256 + t + NCONS] + part[1 * 256 + t + NCONS];
        float r0 = (cnt > 0) ? (0.9f * p0 + s0 * inv) : p0;
        float r1 = (cnt > 0) ? (0.9f * p1 + s1 * inv) : p1;
        out[c * FEAT_DIM + t]         = r0;
        out[c * FEAT_DIM + t + NCONS] = r1;
    }
}

// ---------------------------------------------------------------------------
// Launch: two kernels total.
// ---------------------------------------------------------------------------
extern "C" void kernel_launch(void* const* d_in, const int* in_sizes, int n_in,
                              void* d_out, int out_size) {
    const float* features   = (const float*)d_in[0];
    const int*   labels     = (const int*)d_in[1];
    const float* prototypes = (const float*)d_in[2];
    float*       out        = (float*)d_out;

    int n   = in_sizes[1];
    int rpb = (n + NBLK - 1) / NBLK;   // rows per block-chunk (1024)

    k_prep  <<<NBLK, 1024>>>(labels, n, rpb);
    k_reduce<<<NUM_CLASSES, 160>>>((const char*)features, prototypes, out);
}

// round 14
// speedup vs baseline: 1.2040x; 1.0012x over previous
#include <cuda_runtime.h>
#include <cstdint>

#define NUM_CLASSES 1000
#define FEAT_DIM    256
#define NROWS       262144
#define NBLK        256          // row chunks (one fused-scatter block each)
#define CAP         512          // bucket capacity per class (max count ~330)
#define LAB_CAP     2048         // smem label cache capacity

#define NSTAGE      3            // pipeline stages in the reduce
#define RPS         8            // rows per stage (8 KB)
#define ROW_BYTES   1024         // FEAT_DIM * 4
#define NCONS       128          // consumer threads (4 warps)

// Device-global scratch (no allocation allowed in kernel_launch).
// g_count starts zeroed (static init) and is re-zeroed by k_reduce each call,
// so graph replays always begin from a clean state.
__device__ alignas(16) int g_count[NUM_CLASSES];
__device__ int g_idx[NUM_CLASSES * CAP];     // 2 MB bucket array

// ---------------------------------------------------------------------------
// mbarrier / bulk-async / PDL helpers
// ---------------------------------------------------------------------------
__device__ __forceinline__ uint32_t s2u(const void* p) {
    return (uint32_t)__cvta_generic_to_shared(p);
}
__device__ __forceinline__ void mbar_init(uint32_t a, uint32_t cnt) {
    asm volatile("mbarrier.init.shared.b64 [%0], %1;" :: "r"(a), "r"(cnt) : "memory");
}
__device__ __forceinline__ void mbar_expect_tx(uint32_t a, uint32_t bytes) {
    asm volatile("mbarrier.arrive.expect_tx.shared.b64 _, [%0], %1;"
                 :: "r"(a), "r"(bytes) : "memory");
}
__device__ __forceinline__ void mbar_arrive(uint32_t a) {
    asm volatile("mbarrier.arrive.shared.b64 _, [%0];" :: "r"(a) : "memory");
}
__device__ __forceinline__ void mbar_wait(uint32_t a, uint32_t parity) {
    asm volatile(
        "{\n\t.reg .pred P;\n"
        "WL%=:\n\t"
        "mbarrier.try_wait.parity.acquire.cta.shared::cta.b64 P, [%0], %1;\n\t"
        "@P bra WD%=;\n\t"
        "bra WL%=;\n"
        "WD%=:\n\t}"
        :: "r"(a), "r"(parity) : "memory");
}
__device__ __forceinline__ void bulk_ld(uint32_t dst, const void* src,
                                        uint32_t bytes, uint32_t mbar) {
    asm volatile(
        "cp.async.bulk.shared::cta.global.mbarrier::complete_tx::bytes "
        "[%0], [%1], %2, [%3];"
        :: "r"(dst), "l"(src), "r"(bytes), "r"(mbar) : "memory");
}
__device__ __forceinline__ void pdl_wait() {
    asm volatile("griddepcontrol.wait;" ::: "memory");
}
__device__ __forceinline__ void pdl_trigger() {
    asm volatile("griddepcontrol.launch_dependents;" ::: "memory");
}

// ---------------------------------------------------------------------------
// Kernel 1 (fused prep): per-chunk hist -> bucket reservation -> scatter.
// 256 blocks x 1024 threads, one row per thread. (R12/R13 proven version.)
// ---------------------------------------------------------------------------
__global__ void __launch_bounds__(1024)
k_prep(const int* __restrict__ labels, int n, int rpb) {
    __shared__ int h[NUM_CLASSES];
    __shared__ int lab[LAB_CAP];
    int b = blockIdx.x;
    int t = threadIdx.x;
    int base = b * rpb;
    bool cache = (rpb <= LAB_CAP);

    for (int i = t; i < NUM_CLASSES; i += 1024) h[i] = 0;
    __syncthreads();

    // Phase A: histogram + label caching.
    for (int j = t; j < rpb; j += 1024) {
        int r = base + j;
        int c = (r < n) ? labels[r] : -1;
        if (cache) lab[j] = c;
        if (c >= 0) atomicAdd(&h[c], 1);
    }
    __syncthreads();

    // Phase B: reserve ranges; h[c] becomes this block's cursor base.
    for (int c = t; c < NUM_CLASSES; c += 1024) {
        int v = h[c];
        h[c] = (v > 0) ? atomicAdd(&g_count[c], v) : 0;
    }
    __syncthreads();

    // Phase C: scatter (labels from smem).
    for (int j = t; j < rpb; j += 1024) {
        int r = base + j;
        if (r < n) {
            int c = cache ? lab[j] : labels[r];
            int pos = atomicAdd(&h[c], 1);
            g_idx[c * CAP + pos] = r;
        }
    }
    // PDL: allow the dependent k_reduce grid to launch; memory visibility for
    // dependents is guaranteed at their griddepcontrol.wait after this block's
    // writes complete (all blocks must trigger/finish before wait releases).
    pdl_trigger();
}

// ---------------------------------------------------------------------------
// Kernel 2: warp-specialized pipelined reduce (proven R12 mainloop) with a
// PDL prolog: mbarrier init + prototype prefetch run BEFORE the dependency
// wait, overlapping with k_prep's tail and the launch latency.
// ---------------------------------------------------------------------------
__global__ void __launch_bounds__(160, 8)
k_reduce(const char* __restrict__ featsB,
         const float* __restrict__ protos,
         float* __restrict__ out) {
    __shared__ float4 stage[NSTAGE][RPS * 64];          // 3 x 8KB
    __shared__ float4 part4[2][64];                     // 2KB combine buffer
    __shared__ alignas(8) unsigned long long mbar[2 * NSTAGE]; // full/empty pairs

    int c = blockIdx.x;
    int t = threadIdx.x;
    int start = c * CAP;

    // ---- PDL prolog: independent of k_prep's outputs ----
    float p0 = 0.f, p1 = 0.f;
    if (t < NCONS) {
        p0 = protos[c * FEAT_DIM + t];
        p1 = protos[c * FEAT_DIM + t + NCONS];
    }
    if (t == 0) {
        #pragma unroll
        for (int s = 0; s < NSTAGE; s++) {
            mbar_init(s2u(&mbar[2 * s]), 1);        // full: tx-completion
            mbar_init(s2u(&mbar[2 * s + 1]), 4);    // empty: 4 consumer warps
        }
    }
    __syncthreads();

    // ---- wait for k_prep to finish, then read its outputs ----
    pdl_wait();
    int cnt   = g_count[c];
    int nIter = (cnt + RPS - 1) / RPS;
    __syncthreads();
    // All threads will re-read cnt themselves; reset after a sync so every
    // thread's read of g_count[c] (above, per-thread) precedes the store.
    if (t == 0) g_count[c] = 0;

    if (t >= NCONS) {
        // ---- producer warp ----
        int lane = t - NCONS;
        int idxReg = 0;
        int s = 0, wrap = 0;
        for (int i = 0; i < nIter; i++) {
            if ((i & 3) == 0) {           // refill 32 indices (4 iterations worth)
                int p = i * RPS + lane;
                idxReg = (p < cnt) ? g_idx[start + p] : 0;
            }
            if (wrap > 0)
                mbar_wait(s2u(&mbar[2 * s + 1]), (unsigned)((wrap - 1) & 1));
            int m = min(RPS, cnt - i * RPS);
            int row = __shfl_sync(0xffffffffu, idxReg, ((i & 3) << 3) + (lane & 7));
            if (lane == 0)
                mbar_expect_tx(s2u(&mbar[2 * s]), (uint32_t)m * ROW_BYTES);
            __syncwarp();
            if (lane < m)
                bulk_ld(s2u(&stage[s][0]) + (uint32_t)lane * ROW_BYTES,
                        featsB + (long)row * ROW_BYTES,
                        ROW_BYTES, s2u(&mbar[2 * s]));
            if (++s == NSTAGE) { s = 0; wrap++; }
        }
    } else {
        // ---- consumer warps (4 warps, 128 threads) ----
        int grp = t >> 6;     // 0..1
        int col = t & 63;
        float4 a0 = make_float4(0.f, 0.f, 0.f, 0.f);
        float4 a1 = make_float4(0.f, 0.f, 0.f, 0.f);
        float4 a2 = make_float4(0.f, 0.f, 0.f, 0.f);
        float4 a3 = make_float4(0.f, 0.f, 0.f, 0.f);
        int s = 0, ph = 0;
        for (int i = 0; i < nIter; i++) {
            mbar_wait(s2u(&mbar[2 * s]), (unsigned)ph);
            int m = min(RPS, cnt - i * RPS);
            if (grp < m) {
                float4 v = stage[s][grp * 64 + col];
                a0.x += v.x; a0.y += v.y; a0.z += v.z; a0.w += v.w;
            }
            if (grp + 2 < m) {
                float4 v = stage[s][(grp + 2) * 64 + col];
                a1.x += v.x; a1.y += v.y; a1.z += v.z; a1.w += v.w;
            }
            if (grp + 4 < m) {
                float4 v = stage[s][(grp + 4) * 64 + col];
                a2.x += v.x; a2.y += v.y; a2.z += v.z; a2.w += v.w;
            }
            if (grp + 6 < m) {
                float4 v = stage[s][(grp + 6) * 64 + col];
                a3.x += v.x; a3.y += v.y; a3.z += v.z; a3.w += v.w;
            }
            __syncwarp();
            if ((t & 31) == 0) mbar_arrive(s2u(&mbar[2 * s + 1]));
            if (++s == NSTAGE) { s = 0; ph ^= 1; }
        }
        float4 a = make_float4((a0.x + a1.x) + (a2.x + a3.x),
                               (a0.y + a1.y) + (a2.y + a3.y),
                               (a0.z + a1.z) + (a2.z + a3.z),
                               (a0.w + a1.w) + (a2.w + a3.w));
        part4[grp][col] = a;
    }

    __syncthreads();

    if (t < NCONS) {
        const float* part = (const float*)part4;   // part[g*256 + column]
        float inv = (cnt > 0) ? 0.1f / (float)cnt : 0.f;
        float s0 = part[0 * 256 + t] + part[1 * 256 + t];
        float s1 = part[0 * 256 + t + NCONS] + part[1 * 256 + t + NCONS];
        float r0 = (cnt > 0) ? (0.9f * p0 + s0 * inv) : p0;
        float r1 = (cnt > 0) ? (0.9f * p1 + s1 * inv) : p1;
        out[c * FEAT_DIM + t]         = r0;
        out[c * FEAT_DIM + t + NCONS] = r1;
    }
}

// ---------------------------------------------------------------------------
// Launch: k_prep, then k_reduce with programmatic dependent launch so its
// prolog overlaps k_prep's tail.
// ---------------------------------------------------------------------------
extern "C" void kernel_launch(void* const* d_in, const int* in_sizes, int n_in,
                              void* d_out, int out_size) {
    const float* features   = (const float*)d_in[0];
    const int*   labels     = (const int*)d_in[1];
    const float* prototypes = (const float*)d_in[2];
    float*       out        = (float*)d_out;

    int n   = in_sizes[1];
    int rpb = (n + NBLK - 1) / NBLK;   // rows per block-chunk (1024)

    k_prep<<<NBLK, 1024>>>(labels, n, rpb);

    cudaLaunchConfig_t cfg = {};
    cfg.gridDim  = dim3(NUM_CLASSES, 1, 1);
    cfg.blockDim = dim3(160, 1, 1);
    cfg.dynamicSmemBytes = 0;
    cudaLaunchAttribute attrs[1];
    attrs[0].id = cudaLaunchAttributeProgrammaticStreamSerialization;
    attrs[0].val.programmaticStreamSerializationAllowed = 1;
    cfg.attrs = attrs;
    cfg.numAttrs = 1;
    cudaLaunchKernelEx(&cfg, k_reduce, (const char*)features, prototypes, out);
}